// round 1
// baseline (speedup 1.0000x reference)
#include <cuda_runtime.h>
#include <math.h>

// Problem shape (fixed by setup_inputs): N=50000, C=16, D=3, E=1600000, 2 steps.
#define NMAX 50000
#define CMAX 16
#define N_STEPS 2
#define EPS64 2.220446049250313e-16f

// Scratch (device globals — no allocations allowed).
__device__ float  g_deg[NMAX];                 // weighted out-degree per node
__device__ float4 g_agg[NMAX * CMAX];          // padded accumulator [N, C, 4]
__device__ float  g_xbuf[NMAX * CMAX * 3];     // intermediate x after step 0

// ---------------------------------------------------------------------------
// Zero scratch. nDeg may be 0 (inter-step zero of agg only).
__global__ void zero_kernel(int nAgg, int nDeg) {
    int i = blockIdx.x * blockDim.x + threadIdx.x;
    if (i < nAgg) g_agg[i] = make_float4(0.f, 0.f, 0.f, 0.f);
    if (i < nDeg) g_deg[i] = 0.f;
}

// ---------------------------------------------------------------------------
// deg[s] += w[e]  (once per launch)
__global__ void deg_kernel(const int* __restrict__ senders,
                           const float* __restrict__ w, int E) {
    int e = blockIdx.x * blockDim.x + threadIdx.x;
    if (e < E) atomicAdd(&g_deg[senders[e]], w[e]);
}

// ---------------------------------------------------------------------------
// Edge pass: one thread per (edge, channel). 16 consecutive lanes = one edge,
// so node-row gathers (192B) are coalesced and index loads broadcast.
// Accumulates w * log_p(q) into g_agg[sender] with a single float4 RED.
__global__ void edge_kernel(const float* __restrict__ xin,   // null -> g_xbuf
                            const int* __restrict__ senders,
                            const int* __restrict__ receivers,
                            const float* __restrict__ w,
                            int E, int C) {
    int tid = blockIdx.x * blockDim.x + threadIdx.x;
    if (tid >= E * C) return;
    const float* x = xin ? xin : g_xbuf;

    int e = tid / C;
    int c = tid - e * C;

    int   s  = __ldg(&senders[e]);
    int   r  = __ldg(&receivers[e]);
    float we = __ldg(&w[e]);

    const float* pp = x + (s * C + c) * 3;
    const float* qq = x + (r * C + c) * 3;
    float p0 = pp[0], p1 = pp[1], p2 = pp[2];
    float q0 = qq[0], q1 = qq[1], q2 = qq[2];

    float cs = p0 * q0 + p1 * q1 + p2 * q2;
    cs = fminf(1.0f, fmaxf(-1.0f, cs));
    float u0 = q0 - cs * p0;
    float u1 = q1 - cs * p1;
    float u2 = q2 - cs * p2;
    float un = sqrtf(u0 * u0 + u1 * u1 + u2 * u2);
    float theta = acosf(cs);
    float coef = we * theta / (un + 1e-12f);

    float4 add = make_float4(coef * u0, coef * u1, coef * u2, 0.f);
    atomicAdd(&g_agg[s * C + c], add);   // sm_90+ vector RED
}

// ---------------------------------------------------------------------------
// Node pass: one thread per (node, channel). Applies the sigmoid-clipped step
// and the sphere exp-map, writes the next x.
__global__ void node_kernel(const float* __restrict__ xin,   // null -> g_xbuf
                            float* __restrict__ xout,        // null -> g_xbuf
                            const float* __restrict__ t_sqrt,
                            const float* __restrict__ delta_sqrt,
                            int N, int C) {
    int tid = blockIdx.x * blockDim.x + threadIdx.x;
    if (tid >= N * C) return;
    const float* xi = xin ? xin : g_xbuf;
    float* xo = xout ? xout : g_xbuf;

    int n = tid / C;
    int c = tid - n * C;

    float4 a  = g_agg[tid];
    float deg = g_deg[n];
    float inv = 1.0f / (deg + 1e-12f);

    // v = laplace(x) = -agg/deg
    float v0 = -a.x * inv;
    float v1 = -a.y * inv;
    float v2 = -a.z * inv;

    float nrm = sqrtf(v0 * v0 + v1 * v1 + v2 * v2 + EPS64);

    float dlt = delta_sqrt[c]; dlt *= dlt;
    float alp = 1.0f / (1.0f + expf(-(nrm - dlt)));
    float scale = (nrm * alp <= 1.0f) ? alp : (1.0f / nrm);

    float t = t_sqrt[c]; t = t * t * (1.0f / (float)N_STEPS);
    float f = -scale * t;      // v_final = -(v*scale)*t
    v0 *= f; v1 *= f; v2 *= f;

    // exp map on the sphere
    const float* pp = xi + tid * 3;
    float p0 = pp[0], p1 = pp[1], p2 = pp[2];

    float nv = sqrtf(v0 * v0 + v1 * v1 + v2 * v2);
    float cn = cosf(nv);
    float sn = (nv > 1e-12f) ? (sinf(nv) / nv) : 1.0f;   // sin(n)/n

    float x0 = cn * p0 + sn * v0;
    float x1 = cn * p1 + sn * v1;
    float x2 = cn * p2 + sn * v2;
    float rin = rsqrtf(x0 * x0 + x1 * x1 + x2 * x2);

    xo[tid * 3 + 0] = x0 * rin;
    xo[tid * 3 + 1] = x1 * rin;
    xo[tid * 3 + 2] = x2 * rin;
}

// ---------------------------------------------------------------------------
extern "C" void kernel_launch(void* const* d_in, const int* in_sizes, int n_in,
                              void* d_out, int out_size) {
    const float* nodes      = (const float*)d_in[0];
    const float* edge_w     = (const float*)d_in[1];
    const float* t_sqrt     = (const float*)d_in[2];
    const float* delta_sqrt = (const float*)d_in[3];
    const int*   senders    = (const int*)d_in[4];
    const int*   receivers  = (const int*)d_in[5];
    float*       out        = (float*)d_out;

    const int E = in_sizes[1];
    const int C = in_sizes[2];
    const int N = in_sizes[0] / (C * 3);

    const int TB = 256;
    int nAgg = N * C;
    int zgrid = (nAgg > N ? nAgg : N + TB - 1 + 0);
    zgrid = ((nAgg > N ? nAgg : N) + TB - 1) / TB;
    int egrid = (E * C + TB - 1) / TB;
    int ngrid = (N * C + TB - 1) / TB;
    int dgrid = (E + TB - 1) / TB;

    // deg + agg zero, then degree accumulation (once)
    zero_kernel<<<zgrid, TB>>>(nAgg, N);
    deg_kernel<<<dgrid, TB>>>(senders, edge_w, E);

    // step 0: x = nodes -> g_xbuf
    edge_kernel<<<egrid, TB>>>(nodes, senders, receivers, edge_w, E, C);
    node_kernel<<<ngrid, TB>>>(nodes, /*xout=*/nullptr, t_sqrt, delta_sqrt, N, C);

    // step 1: x = g_xbuf -> out
    zero_kernel<<<(nAgg + TB - 1) / TB, TB>>>(nAgg, 0);
    edge_kernel<<<egrid, TB>>>(nullptr, senders, receivers, edge_w, E, C);
    node_kernel<<<ngrid, TB>>>(nullptr, out, t_sqrt, delta_sqrt, N, C);
}

// round 3
// speedup vs baseline: 1.4314x; 1.4314x over previous
#include <cuda_runtime.h>
#include <math.h>

// Problem shape (fixed by setup_inputs): N=50000, C=16, D=3, E=1600000, 2 steps.
#define NMAX 50000
#define EMAX 1600000
#define CDIM 16
#define N_STEPS 2
#define EPS64 2.220446049250313e-16f
#define SCAN_T 1024

// Scratch (device globals — no allocations allowed).
__device__ int   g_count[NMAX];        // per-sender edge count
__device__ int   g_off[NMAX + 1];      // CSR row offsets
__device__ int   g_cursor[NMAX];       // scatter cursors
__device__ int2  g_csr[EMAX];          // {receiver, weight-as-bits} grouped by sender
__device__ float g_xbuf[NMAX * CDIM * 3];  // intermediate x after step 0

// ---------------------------------------------------------------------------
__global__ void zero_counts(int N) {
    int i = blockIdx.x * blockDim.x + threadIdx.x;
    if (i < N) g_count[i] = 0;
}

__global__ void hist_kernel(const int* __restrict__ senders, int E) {
    int e = blockIdx.x * blockDim.x + threadIdx.x;
    if (e < E) atomicAdd(&g_count[senders[e]], 1);
}

// Single-block exclusive scan over counts -> offsets (+ cursor copy).
__global__ void scan_kernel(int N) {
    __shared__ int sh[SCAN_T];
    int tid = threadIdx.x;
    int chunk = (N + SCAN_T - 1) / SCAN_T;
    int start = tid * chunk;
    int end = min(start + chunk, N);

    int s = 0;
    for (int i = start; i < end; ++i) s += g_count[i];
    sh[tid] = s;
    __syncthreads();

    // Hillis–Steele inclusive scan of per-thread sums
    for (int d = 1; d < SCAN_T; d <<= 1) {
        int v = (tid >= d) ? sh[tid - d] : 0;
        __syncthreads();
        sh[tid] += v;
        __syncthreads();
    }

    int run = (tid == 0) ? 0 : sh[tid - 1];
    for (int i = start; i < end; ++i) {
        g_off[i] = run;
        g_cursor[i] = run;
        run += g_count[i];
    }
    if (start < N && end == N) g_off[N] = run;  // total
}

__global__ void scatter_kernel(const int* __restrict__ senders,
                               const int* __restrict__ receivers,
                               const float* __restrict__ w, int E) {
    int e = blockIdx.x * blockDim.x + threadIdx.x;
    if (e < E) {
        int s = senders[e];
        int pos = atomicAdd(&g_cursor[s], 1);
        g_csr[pos] = make_int2(receivers[e], __float_as_int(w[e]));
    }
}

// ---------------------------------------------------------------------------
// Fused step: thread = (node, channel). 16 consecutive lanes share one node,
// so CSR entries broadcast across the half-warp and q-row gathers coalesce
// into one 192B line per edge per half-warp. Accumulates the weighted log-map
// sum AND the weighted degree in registers, then applies the sigmoid-clipped
// Euler step + sphere exp-map in place. No atomics, no intermediate arrays.
__global__ void step_kernel(const float* __restrict__ xin,   // null -> g_xbuf
                            float* __restrict__ xout,        // null -> g_xbuf
                            const float* __restrict__ t_sqrt,
                            const float* __restrict__ delta_sqrt,
                            int N) {
    int tid = blockIdx.x * blockDim.x + threadIdx.x;
    if (tid >= N * CDIM) return;
    const float* xi = xin ? xin : g_xbuf;
    float* xo = xout ? xout : g_xbuf;

    int n = tid >> 4;         // CDIM == 16
    int c = tid & 15;

    const float* pp = xi + tid * 3;
    float p0 = pp[0], p1 = pp[1], p2 = pp[2];

    int beg = g_off[n];
    int end = g_off[n + 1];

    float a0 = 0.f, a1 = 0.f, a2 = 0.f, sumw = 0.f;

    #pragma unroll 2
    for (int k = beg; k < end; ++k) {
        int2 ew = __ldg(&g_csr[k]);
        int r = ew.x;
        float we = __int_as_float(ew.y);

        const float* qq = xi + (r * CDIM + c) * 3;
        float q0 = __ldg(qq), q1 = __ldg(qq + 1), q2 = __ldg(qq + 2);

        float cs = p0 * q0 + p1 * q1 + p2 * q2;
        cs = fminf(1.0f, fmaxf(-1.0f, cs));
        float u0 = q0 - cs * p0;
        float u1 = q1 - cs * p1;
        float u2 = q2 - cs * p2;
        float un = sqrtf(u0 * u0 + u1 * u1 + u2 * u2);
        float theta = acosf(cs);
        float coef = we * theta / (un + 1e-12f);

        a0 += coef * u0;
        a1 += coef * u1;
        a2 += coef * u2;
        sumw += we;
    }

    // v = laplace = -agg/deg ; v_final = -(v*scale)*t = (agg/deg)*scale*t
    float inv = 1.0f / (sumw + 1e-12f);
    float v0 = -a0 * inv, v1 = -a1 * inv, v2 = -a2 * inv;

    float nrm = sqrtf(v0 * v0 + v1 * v1 + v2 * v2 + EPS64);

    float dlt = __ldg(&delta_sqrt[c]); dlt *= dlt;
    float alp = 1.0f / (1.0f + expf(-(nrm - dlt)));
    float scale = (nrm * alp <= 1.0f) ? alp : (1.0f / nrm);

    float t = __ldg(&t_sqrt[c]); t = t * t * (1.0f / (float)N_STEPS);
    float f = -scale * t;
    v0 *= f; v1 *= f; v2 *= f;

    float nv = sqrtf(v0 * v0 + v1 * v1 + v2 * v2);
    float cn = cosf(nv);
    float sn = (nv > 1e-12f) ? (sinf(nv) / nv) : 1.0f;   // sin(n)/n

    float x0 = cn * p0 + sn * v0;
    float x1 = cn * p1 + sn * v1;
    float x2 = cn * p2 + sn * v2;
    float rin = rsqrtf(x0 * x0 + x1 * x1 + x2 * x2);

    xo[tid * 3 + 0] = x0 * rin;
    xo[tid * 3 + 1] = x1 * rin;
    xo[tid * 3 + 2] = x2 * rin;
}

// ---------------------------------------------------------------------------
extern "C" void kernel_launch(void* const* d_in, const int* in_sizes, int n_in,
                              void* d_out, int out_size) {
    const float* nodes      = (const float*)d_in[0];
    const float* edge_w     = (const float*)d_in[1];
    const float* t_sqrt     = (const float*)d_in[2];
    const float* delta_sqrt = (const float*)d_in[3];
    const int*   senders    = (const int*)d_in[4];
    const int*   receivers  = (const int*)d_in[5];
    float*       out        = (float*)d_out;

    const int E = in_sizes[1];
    const int C = in_sizes[2];
    const int N = in_sizes[0] / (C * 3);

    const int TB = 256;
    int ngrid  = (N + TB - 1) / TB;
    int egrid  = (E + TB - 1) / TB;
    int sgrid  = (N * CDIM + TB - 1) / TB;

    // Build CSR (per launch; deterministic w.r.t. inputs)
    zero_counts<<<ngrid, TB>>>(N);
    hist_kernel<<<egrid, TB>>>(senders, E);
    scan_kernel<<<1, SCAN_T>>>(N);
    scatter_kernel<<<egrid, TB>>>(senders, receivers, edge_w, E);

    // Two fused Euler steps
    step_kernel<<<sgrid, TB>>>(nodes, /*xout=*/nullptr, t_sqrt, delta_sqrt, N);
    step_kernel<<<sgrid, TB>>>(nullptr, out, t_sqrt, delta_sqrt, N);
}

// round 4
// speedup vs baseline: 1.5516x; 1.0840x over previous
#include <cuda_runtime.h>
#include <math.h>

// Problem shape (fixed by setup_inputs): N=50000, C=16, D=3, E=1600000, 2 steps.
#define NMAX 50000
#define EMAX 1600000
#define CDIM 16
#define N_STEPS 2
#define EPS64 2.220446049250313e-16f
#define SCAN_T 1024
#define PI_F 3.14159265358979f

// Scratch (device globals — no allocations allowed).
__device__ int    g_count[NMAX];
__device__ int    g_off[NMAX + 1];
__device__ int    g_cursor[NMAX];
__device__ int2   g_csr[EMAX];                // {receiver, weight bits} grouped by sender
__device__ float4 g_xa[NMAX * CDIM];          // padded x, step-0 input
__device__ float4 g_xb[NMAX * CDIM];          // padded x, step-0 output / step-1 input

// ---------------------------------------------------------------------------
// A&S 4.4.45 acos approximation, |abs err| <= 6.7e-5 rad over [-1,1].
__device__ __forceinline__ float fast_acos(float x) {
    float ax = fabsf(x);
    float p = fmaf(ax, -0.0187293f, 0.0742610f);
    p = fmaf(ax, -p, 0.2121144f);          // note sign fold: a1 + a2*x + a3*x^2 form
    p = fmaf(ax, -p, 1.5707288f);
    float th = sqrtf(1.0f - ax) * p;
    return (x >= 0.0f) ? th : (PI_F - th);
}

// ---------------------------------------------------------------------------
__global__ void pack_kernel(const float* __restrict__ nodes, int NC) {
    int i = blockIdx.x * blockDim.x + threadIdx.x;
    if (i < NC) {
        const float* s = nodes + i * 3;
        g_xa[i] = make_float4(s[0], s[1], s[2], 0.f);
    }
}

__global__ void zero_counts(int N) {
    int i = blockIdx.x * blockDim.x + threadIdx.x;
    if (i < N) g_count[i] = 0;
}

// 4 independent edges per thread -> batched atomics (hide ATOMG latency).
__global__ void hist_kernel(const int* __restrict__ senders, int E) {
    int base = (blockIdx.x * blockDim.x + threadIdx.x) * 4;
    #pragma unroll
    for (int j = 0; j < 4; ++j) {
        int e = base + j;
        if (e < E) atomicAdd(&g_count[senders[e]], 1);
    }
}

// Single-block exclusive scan over counts -> offsets (+ cursor copy).
__global__ void scan_kernel(int N) {
    __shared__ int sh[SCAN_T];
    int tid = threadIdx.x;
    int chunk = (N + SCAN_T - 1) / SCAN_T;
    int start = tid * chunk;
    int end = min(start + chunk, N);

    int s = 0;
    #pragma unroll 8
    for (int i = start; i < end; ++i) s += g_count[i];
    sh[tid] = s;
    __syncthreads();

    for (int d = 1; d < SCAN_T; d <<= 1) {
        int v = (tid >= d) ? sh[tid - d] : 0;
        __syncthreads();
        sh[tid] += v;
        __syncthreads();
    }

    int run = (tid == 0) ? 0 : sh[tid - 1];
    for (int i = start; i < end; ++i) {
        g_off[i] = run;
        g_cursor[i] = run;
        run += g_count[i];
    }
    if (start < N && end == N) g_off[N] = run;
}

// 4 independent edges per thread -> 4 overlapped atomic->store chains.
__global__ void scatter_kernel(const int* __restrict__ senders,
                               const int* __restrict__ receivers,
                               const float* __restrict__ w, int E) {
    int base = (blockIdx.x * blockDim.x + threadIdx.x) * 4;
    int  pos[4]; int2 val[4]; int cnt = 0;
    #pragma unroll
    for (int j = 0; j < 4; ++j) {
        int e = base + j;
        if (e < E) {
            int s = senders[e];
            pos[cnt] = atomicAdd(&g_cursor[s], 1);
            val[cnt] = make_int2(receivers[e], __float_as_int(w[e]));
            ++cnt;
        }
    }
    for (int j = 0; j < cnt; ++j) g_csr[pos[j]] = val[j];
}

// ---------------------------------------------------------------------------
// Fused Euler step. Thread = (node, channel); 16 lanes share one node.
// first: read g_xa, else g_xb. out==null: write padded g_xb, else packed out.
__global__ void step_kernel(int first, float* __restrict__ out,
                            const float* __restrict__ t_sqrt,
                            const float* __restrict__ delta_sqrt,
                            int N) {
    int tid = blockIdx.x * blockDim.x + threadIdx.x;
    if (tid >= N * CDIM) return;
    const float4* xi = first ? g_xa : g_xb;

    int n = tid >> 4;
    int c = tid & 15;

    float4 p = xi[tid];
    float p0 = p.x, p1 = p.y, p2 = p.z;

    int beg = g_off[n];
    int end = g_off[n + 1];

    float a0 = 0.f, a1 = 0.f, a2 = 0.f, sumw = 0.f;

    #pragma unroll 4
    for (int k = beg; k < end; ++k) {
        int2 ew = __ldg(&g_csr[k]);
        float we = __int_as_float(ew.y);
        float4 q = __ldg(&xi[ew.x * CDIM + c]);

        float cs = fmaf(p0, q.x, fmaf(p1, q.y, p2 * q.z));
        cs = fminf(1.0f, fmaxf(-1.0f, cs));
        float u0 = fmaf(-cs, p0, q.x);
        float u1 = fmaf(-cs, p1, q.y);
        float u2 = fmaf(-cs, p2, q.z);
        float un2 = fmaf(u0, u0, fmaf(u1, u1, u2 * u2));
        float un = un2 * rsqrtf(fmaxf(un2, 1e-30f));   // = ||u||, 0-safe
        float theta = fast_acos(cs);
        float coef = __fdividef(we * theta, un + 1e-12f);

        a0 = fmaf(coef, u0, a0);
        a1 = fmaf(coef, u1, a1);
        a2 = fmaf(coef, u2, a2);
        sumw += we;
    }

    // v = -agg/deg ; v_final = -(v*scale)*t
    float inv = __fdividef(1.0f, sumw + 1e-12f);
    float v0 = -a0 * inv, v1 = -a1 * inv, v2 = -a2 * inv;

    float nrm = sqrtf(fmaf(v0, v0, fmaf(v1, v1, v2 * v2)) + EPS64);

    float dlt = __ldg(&delta_sqrt[c]); dlt *= dlt;
    float alp = __fdividef(1.0f, 1.0f + __expf(dlt - nrm));
    float scale = (nrm * alp <= 1.0f) ? alp : __fdividef(1.0f, nrm);

    float t = __ldg(&t_sqrt[c]); t = t * t * (1.0f / (float)N_STEPS);
    float f = -scale * t;
    v0 *= f; v1 *= f; v2 *= f;

    float nv = sqrtf(fmaf(v0, v0, fmaf(v1, v1, v2 * v2)));
    float cn = __cosf(nv);
    float sn = (nv > 1e-12f) ? __fdividef(__sinf(nv), nv) : 1.0f;

    float x0 = fmaf(cn, p0, sn * v0);
    float x1 = fmaf(cn, p1, sn * v1);
    float x2 = fmaf(cn, p2, sn * v2);
    float rin = rsqrtf(fmaf(x0, x0, fmaf(x1, x1, x2 * x2)));

    if (out) {
        out[tid * 3 + 0] = x0 * rin;
        out[tid * 3 + 1] = x1 * rin;
        out[tid * 3 + 2] = x2 * rin;
    } else {
        g_xb[tid] = make_float4(x0 * rin, x1 * rin, x2 * rin, 0.f);
    }
}

// ---------------------------------------------------------------------------
extern "C" void kernel_launch(void* const* d_in, const int* in_sizes, int n_in,
                              void* d_out, int out_size) {
    const float* nodes      = (const float*)d_in[0];
    const float* edge_w     = (const float*)d_in[1];
    const float* t_sqrt     = (const float*)d_in[2];
    const float* delta_sqrt = (const float*)d_in[3];
    const int*   senders    = (const int*)d_in[4];
    const int*   receivers  = (const int*)d_in[5];
    float*       out        = (float*)d_out;

    const int E = in_sizes[1];
    const int C = in_sizes[2];
    const int N = in_sizes[0] / (C * 3);
    const int NC = N * C;

    const int TB = 256;
    int ngrid = (N + TB - 1) / TB;
    int e4    = (E + 4 * TB - 1) / (4 * TB);
    int sgrid = (NC + TB - 1) / TB;

    pack_kernel<<<sgrid, TB>>>(nodes, NC);
    zero_counts<<<ngrid, TB>>>(N);
    hist_kernel<<<e4, TB>>>(senders, E);
    scan_kernel<<<1, SCAN_T>>>(N);
    scatter_kernel<<<e4, TB>>>(senders, receivers, edge_w, E);

    step_kernel<<<sgrid, TB>>>(1, /*out=*/nullptr, t_sqrt, delta_sqrt, N);
    step_kernel<<<sgrid, TB>>>(0, out, t_sqrt, delta_sqrt, N);
}

// round 6
// speedup vs baseline: 2.1364x; 1.3769x over previous
#include <cuda_runtime.h>
#include <math.h>

// Problem shape (fixed by setup_inputs): N=50000, C=16, D=3, E=1600000, 2 steps.
#define NMAX 50000
#define EMAX 1600000
#define CDIM 16
#define N_STEPS 2
#define EPS64 2.220446049250313e-16f
#define PI_F 3.14159265358979f
#define SB 1024                       // scan tile size
#define NBMAX ((NMAX + SB - 1) / SB)  // 49 blocks

// Scratch (device globals — no allocations allowed).
__device__ int    g_count[NMAX];
__device__ int    g_off[NMAX + 1];
__device__ int    g_cursor[NMAX];
__device__ int    g_bsum[NBMAX];
__device__ int    g_bbase[NBMAX];
__device__ int2   g_csr[EMAX];                // {receiver, weight bits} grouped by sender
__device__ float4 g_xa[NMAX * CDIM];          // padded x, step-0 input
__device__ float4 g_xb[NMAX * CDIM];          // padded x, step-0 output / step-1 input

// ---------------------------------------------------------------------------
// A&S 4.4.45 acos approximation, |abs err| <= 6.7e-5 rad over [-1,1].
__device__ __forceinline__ float fast_acos(float x) {
    float ax = fabsf(x);
    float p = fmaf(ax, -0.0187293f, 0.0742610f);
    p = fmaf(ax, -p, 0.2121144f);
    p = fmaf(ax, -p, 1.5707288f);
    float th = sqrtf(1.0f - ax) * p;
    return (x >= 0.0f) ? th : (PI_F - th);
}

// ---------------------------------------------------------------------------
__global__ void pack_kernel(const float* __restrict__ nodes, int NC) {
    int i = blockIdx.x * blockDim.x + threadIdx.x;
    if (i < NC) {
        const float* s = nodes + i * 3;
        g_xa[i] = make_float4(s[0], s[1], s[2], 0.f);
    }
}

__global__ void zero_counts(int N) {
    int i = blockIdx.x * blockDim.x + threadIdx.x;
    if (i < N) g_count[i] = 0;
}

// 4 independent edges per thread -> batched atomics (hide ATOMG latency).
__global__ void hist_kernel(const int* __restrict__ senders, int E) {
    int base = (blockIdx.x * blockDim.x + threadIdx.x) * 4;
    #pragma unroll
    for (int j = 0; j < 4; ++j) {
        int e = base + j;
        if (e < E) atomicAdd(&g_count[senders[e]], 1);
    }
}

// ---------------------------------------------------------------------------
// Device-wide exclusive scan of g_count, 3 phases, all full-chip parallel.

// Phase 1: per-block tree reduction of one SB-wide tile -> g_bsum.
__global__ void blocksum_kernel(int N) {
    __shared__ int sh[SB];
    int tid = threadIdx.x;
    int i = blockIdx.x * SB + tid;
    sh[tid] = (i < N) ? g_count[i] : 0;
    __syncthreads();
    for (int d = SB / 2; d > 0; d >>= 1) {
        if (tid < d) sh[tid] += sh[tid + d];
        __syncthreads();
    }
    if (tid == 0) g_bsum[blockIdx.x] = sh[0];
}

// Phase 2: tiny serial exclusive scan of the ~49 block sums (+ writes total).
__global__ void bscan_kernel(int nb, int N) {
    __shared__ int sh[NBMAX];
    int tid = threadIdx.x;
    if (tid < nb) sh[tid] = g_bsum[tid];
    __syncthreads();
    if (tid == 0) {
        int run = 0;
        for (int b = 0; b < nb; ++b) {
            g_bbase[b] = run;
            run += sh[b];
        }
        g_off[N] = run;   // total edges
    }
}

// Phase 3: block-local exclusive Hillis-Steele scan + block base -> offsets.
__global__ void offsets_kernel(int N) {
    __shared__ int sh[SB];
    int tid = threadIdx.x;
    int i = blockIdx.x * SB + tid;
    int v = (i < N) ? g_count[i] : 0;
    sh[tid] = v;
    __syncthreads();
    #pragma unroll
    for (int d = 1; d < SB; d <<= 1) {
        int t = (tid >= d) ? sh[tid - d] : 0;
        __syncthreads();
        sh[tid] += t;
        __syncthreads();
    }
    if (i < N) {
        int off = g_bbase[blockIdx.x] + sh[tid] - v;   // exclusive
        g_off[i] = off;
        g_cursor[i] = off;
    }
}

// ---------------------------------------------------------------------------
// 4 independent edges per thread -> 4 overlapped atomic->store chains.
__global__ void scatter_kernel(const int* __restrict__ senders,
                               const int* __restrict__ receivers,
                               const float* __restrict__ w, int E) {
    int base = (blockIdx.x * blockDim.x + threadIdx.x) * 4;
    int  pos[4]; int2 val[4]; int cnt = 0;
    #pragma unroll
    for (int j = 0; j < 4; ++j) {
        int e = base + j;
        if (e < E) {
            int s = senders[e];
            pos[cnt] = atomicAdd(&g_cursor[s], 1);
            val[cnt] = make_int2(receivers[e], __float_as_int(w[e]));
            ++cnt;
        }
    }
    for (int j = 0; j < cnt; ++j) g_csr[pos[j]] = val[j];
}

// ---------------------------------------------------------------------------
// Fused Euler step. Thread = (node, channel); 16 lanes share one node.
// first: read g_xa, else g_xb. out==null: write padded g_xb, else packed out.
__global__ void step_kernel(int first, float* __restrict__ out,
                            const float* __restrict__ t_sqrt,
                            const float* __restrict__ delta_sqrt,
                            int N) {
    int tid = blockIdx.x * blockDim.x + threadIdx.x;
    if (tid >= N * CDIM) return;
    const float4* xi = first ? g_xa : g_xb;

    int n = tid >> 4;
    int c = tid & 15;

    float4 p = xi[tid];
    float p0 = p.x, p1 = p.y, p2 = p.z;

    int beg = g_off[n];
    int end = g_off[n + 1];

    float a0 = 0.f, a1 = 0.f, a2 = 0.f, sumw = 0.f;

    #pragma unroll 4
    for (int k = beg; k < end; ++k) {
        int2 ew = __ldg(&g_csr[k]);
        float we = __int_as_float(ew.y);
        float4 q = __ldg(&xi[ew.x * CDIM + c]);

        float cs = fmaf(p0, q.x, fmaf(p1, q.y, p2 * q.z));
        cs = fminf(1.0f, fmaxf(-1.0f, cs));
        float u0 = fmaf(-cs, p0, q.x);
        float u1 = fmaf(-cs, p1, q.y);
        float u2 = fmaf(-cs, p2, q.z);
        float un2 = fmaf(u0, u0, fmaf(u1, u1, u2 * u2));
        float un = un2 * rsqrtf(fmaxf(un2, 1e-30f));   // = ||u||, 0-safe
        float theta = fast_acos(cs);
        float coef = __fdividef(we * theta, un + 1e-12f);

        a0 = fmaf(coef, u0, a0);
        a1 = fmaf(coef, u1, a1);
        a2 = fmaf(coef, u2, a2);
        sumw += we;
    }

    // v = -agg/deg ; v_final = -(v*scale)*t
    float inv = __fdividef(1.0f, sumw + 1e-12f);
    float v0 = -a0 * inv, v1 = -a1 * inv, v2 = -a2 * inv;

    float nrm = sqrtf(fmaf(v0, v0, fmaf(v1, v1, v2 * v2)) + EPS64);

    float dlt = __ldg(&delta_sqrt[c]); dlt *= dlt;
    float alp = __fdividef(1.0f, 1.0f + __expf(dlt - nrm));
    float scale = (nrm * alp <= 1.0f) ? alp : __fdividef(1.0f, nrm);

    float t = __ldg(&t_sqrt[c]); t = t * t * (1.0f / (float)N_STEPS);
    float f = -scale * t;
    v0 *= f; v1 *= f; v2 *= f;

    float nv = sqrtf(fmaf(v0, v0, fmaf(v1, v1, v2 * v2)));
    float cn = __cosf(nv);
    float sn = (nv > 1e-12f) ? __fdividef(__sinf(nv), nv) : 1.0f;

    float x0 = fmaf(cn, p0, sn * v0);
    float x1 = fmaf(cn, p1, sn * v1);
    float x2 = fmaf(cn, p2, sn * v2);
    float rin = rsqrtf(fmaf(x0, x0, fmaf(x1, x1, x2 * x2)));

    if (out) {
        out[tid * 3 + 0] = x0 * rin;
        out[tid * 3 + 1] = x1 * rin;
        out[tid * 3 + 2] = x2 * rin;
    } else {
        g_xb[tid] = make_float4(x0 * rin, x1 * rin, x2 * rin, 0.f);
    }
}

// ---------------------------------------------------------------------------
extern "C" void kernel_launch(void* const* d_in, const int* in_sizes, int n_in,
                              void* d_out, int out_size) {
    const float* nodes      = (const float*)d_in[0];
    const float* edge_w     = (const float*)d_in[1];
    const float* t_sqrt     = (const float*)d_in[2];
    const float* delta_sqrt = (const float*)d_in[3];
    const int*   senders    = (const int*)d_in[4];
    const int*   receivers  = (const int*)d_in[5];
    float*       out        = (float*)d_out;

    const int E = in_sizes[1];
    const int C = in_sizes[2];
    const int N = in_sizes[0] / (C * 3);
    const int NC = N * C;

    const int TB = 256;
    int ngrid = (N + TB - 1) / TB;
    int e4    = (E + 4 * TB - 1) / (4 * TB);
    int sgrid = (NC + TB - 1) / TB;
    int nb    = (N + SB - 1) / SB;

    pack_kernel<<<sgrid, TB>>>(nodes, NC);
    zero_counts<<<ngrid, TB>>>(N);
    hist_kernel<<<e4, TB>>>(senders, E);

    // device-wide exclusive scan (3 phases, all parallel)
    blocksum_kernel<<<nb, SB>>>(N);
    bscan_kernel<<<1, SB>>>(nb, N);
    offsets_kernel<<<nb, SB>>>(N);

    scatter_kernel<<<e4, TB>>>(senders, receivers, edge_w, E);

    step_kernel<<<sgrid, TB>>>(1, /*out=*/nullptr, t_sqrt, delta_sqrt, N);
    step_kernel<<<sgrid, TB>>>(0, out, t_sqrt, delta_sqrt, N);
}